// round 1
// baseline (speedup 1.0000x reference)
#include <cuda_runtime.h>
#include <math.h>

// Problem constants (fixed shapes from reference)
#define HH 224
#define WW 224
#define CC 3
#define LL 256            // B*F = 8*32
#define NOISE_LEN 766     // 3L-2
#define WIN 511           // 2L-1

// Per-frame 3x3 matrices (row-major), produced by kernel 1, consumed by kernel 2.
__device__ float g_M[LL * 9];

// ---------------------------------------------------------------------------
// Kernel 1: smooth noise with symmetric exponential window, build per-frame
// homography M = A @ warp @ Bpre. fp64 internally (weights span ~3.6e10).
// One block, 256 threads, thread l handles frame l.
// ---------------------------------------------------------------------------
__global__ void vrp_compute_matrices(const float* __restrict__ noise,
                                     const float* __restrict__ basis) {
    const int l = threadIdx.x;
    if (l >= LL) return;

    // Correlation with w[k]: w[k] = 1.1^k for k<=254, 1.1^255 at k=255,
    // then mirrored down to 1.1^0 at k=510. (w symmetric -> conv == corr)
    double dot0 = 0.0, dot1 = 0.0, dot2 = 0.0, dot3 = 0.0, wsum = 0.0;
    double p = 1.0;
    for (int k = 0; k < WIN; ++k) {
        wsum += p;
        dot0 += (double)__ldg(noise + 0 * NOISE_LEN + l + k) * p;
        dot1 += (double)__ldg(noise + 1 * NOISE_LEN + l + k) * p;
        dot2 += (double)__ldg(noise + 2 * NOISE_LEN + l + k) * p;
        dot3 += (double)__ldg(noise + 3 * NOISE_LEN + l + k) * p;
        p = (k < LL - 1) ? p * 1.1 : p / 1.1;
    }
    double wv[4];
    wv[0] = dot0 / wsum; wv[1] = dot1 / wsum;
    wv[2] = dot2 / wsum; wv[3] = dot3 / wsum;

    // warp = sum_i max(wv_i,0)*basis_i + (4 - sum_i max(wv_i,0)) * I
    double Wp[9] = {0, 0, 0, 0, 0, 0, 0, 0, 0};
    double s = 0.0;
    #pragma unroll
    for (int i = 0; i < 4; ++i) {
        double v = wv[i] > 0.0 ? wv[i] : 0.0;
        s += v;
        #pragma unroll
        for (int j = 0; j < 9; ++j)
            Wp[j] += v * (double)__ldg(basis + i * 9 + j);
    }
    const double d = 4.0 - s;
    Wp[0] += d; Wp[4] += d; Wp[8] += d;

    // Bpre = T(-0.5,-0.5) @ S(1/223,1/223) = [[1/223,0,-0.5],[0,1/223,-0.5],[0,0,1]]
    const double inv223 = 1.0 / 223.0;
    double T[9];
    #pragma unroll
    for (int i = 0; i < 3; ++i) {
        T[i * 3 + 0] = Wp[i * 3 + 0] * inv223;
        T[i * 3 + 1] = Wp[i * 3 + 1] * inv223;
        T[i * 3 + 2] = -0.5 * Wp[i * 3 + 0] - 0.5 * Wp[i * 3 + 1] + Wp[i * 3 + 2];
    }
    // A = S(223,223) @ T(0.5,0.5) = [[223,0,111.5],[0,223,111.5],[0,0,1]]
    float* Mo = &g_M[l * 9];
    #pragma unroll
    for (int j = 0; j < 3; ++j) {
        Mo[0 * 3 + j] = (float)(223.0 * T[0 * 3 + j] + 111.5 * T[2 * 3 + j]);
        Mo[1 * 3 + j] = (float)(223.0 * T[1 * 3 + j] + 111.5 * T[2 * 3 + j]);
        Mo[2 * 3 + j] = (float)(T[2 * 3 + j]);
    }
}

// ---------------------------------------------------------------------------
// Kernel 2: per-pixel projective warp + bilinear sample (zero fill outside).
// One thread per output pixel; block = 32x8 tile for gather locality.
// ---------------------------------------------------------------------------
__global__ __launch_bounds__(256) void vrp_warp_bilinear(const float* __restrict__ x,
                                                         float* __restrict__ out) {
    const int l = blockIdx.z;
    const int c = blockIdx.x * 32 + threadIdx.x;
    const int r = blockIdx.y * 8 + threadIdx.y;

    __shared__ float Ms[9];
    if (threadIdx.y == 0 && threadIdx.x < 9)
        Ms[threadIdx.x] = g_M[l * 9 + threadIdx.x];
    __syncthreads();

    const float fc = (float)c, fr = (float)r;
    const float px = Ms[0] * fc + Ms[1] * fr + Ms[2];
    const float py = Ms[3] * fc + Ms[4] * fr + Ms[5];
    const float pz = Ms[6] * fc + Ms[7] * fr + Ms[8];
    const float sx = px / pz;
    const float sy = py / pz;

    const float x0 = floorf(sx), y0 = floorf(sy);
    const float wx = sx - x0, wy = sy - y0;

    const float* img = x + (size_t)l * (HH * WW * CC);

    float acc0 = 0.f, acc1 = 0.f, acc2 = 0.f;
    #pragma unroll
    for (int dy = 0; dy < 2; ++dy) {
        #pragma unroll
        for (int dx = 0; dx < 2; ++dx) {
            const float xf = x0 + (float)dx;
            const float yf = y0 + (float)dy;
            const float wgt = (dy ? wy : 1.f - wy) * (dx ? wx : 1.f - wx);
            const bool valid = (xf >= 0.f) && (xf <= (float)(WW - 1)) &&
                               (yf >= 0.f) && (yf <= (float)(HH - 1));
            if (valid) {
                const int xi = (int)xf;
                const int yi = (int)yf;
                const float* p = img + ((size_t)yi * WW + xi) * CC;
                acc0 = fmaf(wgt, __ldg(p + 0), acc0);
                acc1 = fmaf(wgt, __ldg(p + 1), acc1);
                acc2 = fmaf(wgt, __ldg(p + 2), acc2);
            }
        }
    }

    float* o = out + ((size_t)(l * HH + r) * WW + c) * CC;
    o[0] = acc0;
    o[1] = acc1;
    o[2] = acc2;
}

// ---------------------------------------------------------------------------
// Launch: inputs in metadata order: x (f32), noise (f32), warp_basis (f32).
// ---------------------------------------------------------------------------
extern "C" void kernel_launch(void* const* d_in, const int* in_sizes, int n_in,
                              void* d_out, int out_size) {
    const float* x     = (const float*)d_in[0];
    const float* noise = (const float*)d_in[1];
    const float* basis = (const float*)d_in[2];
    float* out = (float*)d_out;

    vrp_compute_matrices<<<1, 256>>>(noise, basis);

    dim3 block(32, 8, 1);
    dim3 grid(WW / 32, HH / 8, LL);  // 7 x 28 x 256
    vrp_warp_bilinear<<<grid, block>>>(x, out);
}

// round 2
// speedup vs baseline: 4.8504x; 4.8504x over previous
#include <cuda_runtime.h>
#include <math.h>

// Problem constants (fixed shapes from reference)
#define HH 224
#define WW 224
#define CC 3
#define LL 256            // B*F = 8*32
#define NOISE_LEN 766     // 3L-2
#define WIN 511           // 2L-1

// Intermediates
__device__ double g_wv[4 * LL];     // smoothed noise values per (row, frame)
__device__ float  g_M[LL * 9];      // per-frame 3x3 homographies (row-major)

// ---------------------------------------------------------------------------
// Kernel 1a: smoothing. One warp per (noise_row, frame) dot product.
// 4*256 = 1024 warps = 128 blocks x 8 warps. Weights staged in shared (fp64).
// ---------------------------------------------------------------------------
__global__ __launch_bounds__(256) void vrp_smooth(const float* __restrict__ noise) {
    __shared__ double w[WIN];
    __shared__ double wsum_s;

    const int tid = threadIdx.x;

    // Build symmetric exponential window: w[k] = 1.1^k for k<256, mirrored after.
    for (int t = tid; t < WIN; t += 256) {
        const int e = (t < LL) ? t : (2 * LL - 2 - t);
        w[t] = pow(1.1, (double)e);
    }
    __syncthreads();

    const int warp = tid >> 5;
    const int lane = tid & 31;
    const int combo = blockIdx.x * 8 + warp;   // 0..1023
    const int frame = combo & (LL - 1);
    const int row   = combo >> 8;              // 0..3

    // wsum (each warp computes it; cheap)
    double wsum = 0.0;
    for (int k = lane; k < WIN; k += 32) wsum = wsum + w[k];

    // dot = sum_k noise[row][frame + k] * w[k]
    const float* nr = noise + row * NOISE_LEN + frame;
    double dot = 0.0;
    for (int k = lane; k < WIN; k += 32)
        dot = fma((double)__ldg(nr + k), w[k], dot);

    // warp reduce (double)
    #pragma unroll
    for (int off = 16; off > 0; off >>= 1) {
        dot  += __shfl_down_sync(0xffffffffu, dot, off);
        wsum += __shfl_down_sync(0xffffffffu, wsum, off);
    }

    if (lane == 0)
        g_wv[row * LL + frame] = dot / wsum;
}

// ---------------------------------------------------------------------------
// Kernel 1b: assemble per-frame homography. 1 block, 256 threads (1 frame each).
// ---------------------------------------------------------------------------
__global__ void vrp_assemble(const float* __restrict__ basis) {
    const int l = threadIdx.x;
    if (l >= LL) return;

    // warp = sum_i max(wv_i,0)*basis_i + (4 - sum_i max(wv_i,0)) * I
    double Wp[9] = {0, 0, 0, 0, 0, 0, 0, 0, 0};
    double s = 0.0;
    #pragma unroll
    for (int i = 0; i < 4; ++i) {
        double v = g_wv[i * LL + l];
        v = v > 0.0 ? v : 0.0;
        s += v;
        #pragma unroll
        for (int j = 0; j < 9; ++j)
            Wp[j] += v * (double)__ldg(basis + i * 9 + j);
    }
    const double d = 4.0 - s;
    Wp[0] += d; Wp[4] += d; Wp[8] += d;

    // Bpre = T(-0.5,-0.5) @ S(1/223,1/223)
    const double inv223 = 1.0 / 223.0;
    double T[9];
    #pragma unroll
    for (int i = 0; i < 3; ++i) {
        T[i * 3 + 0] = Wp[i * 3 + 0] * inv223;
        T[i * 3 + 1] = Wp[i * 3 + 1] * inv223;
        T[i * 3 + 2] = -0.5 * Wp[i * 3 + 0] - 0.5 * Wp[i * 3 + 1] + Wp[i * 3 + 2];
    }
    // A = S(223,223) @ T(0.5,0.5)
    float* Mo = &g_M[l * 9];
    #pragma unroll
    for (int j = 0; j < 3; ++j) {
        Mo[0 * 3 + j] = (float)(223.0 * T[0 * 3 + j] + 111.5 * T[2 * 3 + j]);
        Mo[1 * 3 + j] = (float)(223.0 * T[1 * 3 + j] + 111.5 * T[2 * 3 + j]);
        Mo[2 * 3 + j] = (float)(T[2 * 3 + j]);
    }
}

// ---------------------------------------------------------------------------
// Kernel 2: per-pixel projective warp + bilinear sample (zero fill outside).
// One thread per output pixel; block = 32x8 tile for gather locality.
// ---------------------------------------------------------------------------
__global__ __launch_bounds__(256) void vrp_warp_bilinear(const float* __restrict__ x,
                                                         float* __restrict__ out) {
    const int l = blockIdx.z;
    const int c = blockIdx.x * 32 + threadIdx.x;
    const int r = blockIdx.y * 8 + threadIdx.y;

    __shared__ float Ms[9];
    if (threadIdx.y == 0 && threadIdx.x < 9)
        Ms[threadIdx.x] = g_M[l * 9 + threadIdx.x];
    __syncthreads();

    const float fc = (float)c, fr = (float)r;
    const float px = Ms[0] * fc + Ms[1] * fr + Ms[2];
    const float py = Ms[3] * fc + Ms[4] * fr + Ms[5];
    const float pz = Ms[6] * fc + Ms[7] * fr + Ms[8];
    const float sx = px / pz;
    const float sy = py / pz;

    const float x0 = floorf(sx), y0 = floorf(sy);
    const float wx = sx - x0, wy = sy - y0;

    const float* img = x + (size_t)l * (HH * WW * CC);

    float acc0 = 0.f, acc1 = 0.f, acc2 = 0.f;
    #pragma unroll
    for (int dy = 0; dy < 2; ++dy) {
        #pragma unroll
        for (int dx = 0; dx < 2; ++dx) {
            const float xf = x0 + (float)dx;
            const float yf = y0 + (float)dy;
            const float wgt = (dy ? wy : 1.f - wy) * (dx ? wx : 1.f - wx);
            const bool valid = (xf >= 0.f) && (xf <= (float)(WW - 1)) &&
                               (yf >= 0.f) && (yf <= (float)(HH - 1));
            if (valid) {
                const int xi = (int)xf;
                const int yi = (int)yf;
                const float* p = img + ((size_t)yi * WW + xi) * CC;
                acc0 = fmaf(wgt, __ldg(p + 0), acc0);
                acc1 = fmaf(wgt, __ldg(p + 1), acc1);
                acc2 = fmaf(wgt, __ldg(p + 2), acc2);
            }
        }
    }

    float* o = out + ((size_t)(l * HH + r) * WW + c) * CC;
    o[0] = acc0;
    o[1] = acc1;
    o[2] = acc2;
}

// ---------------------------------------------------------------------------
// Launch: inputs in metadata order: x (f32), noise (f32), warp_basis (f32).
// ---------------------------------------------------------------------------
extern "C" void kernel_launch(void* const* d_in, const int* in_sizes, int n_in,
                              void* d_out, int out_size) {
    const float* x     = (const float*)d_in[0];
    const float* noise = (const float*)d_in[1];
    const float* basis = (const float*)d_in[2];
    float* out = (float*)d_out;

    vrp_smooth<<<128, 256>>>(noise);
    vrp_assemble<<<1, 256>>>(basis);

    dim3 block(32, 8, 1);
    dim3 grid(WW / 32, HH / 8, LL);  // 7 x 28 x 256
    vrp_warp_bilinear<<<grid, block>>>(x, out);
}

// round 3
// speedup vs baseline: 5.9798x; 1.2328x over previous
#include <cuda_runtime.h>
#include <math.h>

// Problem constants (fixed shapes from reference)
#define HH 224
#define WW 224
#define CC 3
#define LL 256            // B*F = 8*32
#define NOISE_LEN 766     // 3L-2
#define WIN 511           // 2L-1
#define FRAME_FLOATS (HH * WW * CC)   // 150528

// Per-frame 3x3 matrices (row-major), produced by kernel 1, consumed by kernel 2.
__device__ float g_M[LL * 9];

// ---------------------------------------------------------------------------
// Kernel 1: fused smoothing + matrix assembly. One block per frame (256 blocks
// of 128 threads). Warp w computes the dot of noise row w with the symmetric
// exponential window (fp64, built via binary exponentiation — no pow()).
// Then 9 threads assemble the homography through shared staging.
// ---------------------------------------------------------------------------
__global__ __launch_bounds__(128) void vrp_matrices(const float* __restrict__ noise,
                                                    const float* __restrict__ basis) {
    __shared__ double w[WIN];
    __shared__ double wv_sh[4];
    __shared__ double vmax[4];
    __shared__ double wp_sh[9];
    __shared__ double wsum_sh;

    const int tid = threadIdx.x;
    const int frame = blockIdx.x;

    // Binary powers of 1.1: sq[b] = 1.1^(2^b)
    double sq[8];
    sq[0] = 1.1;
    #pragma unroll
    for (int b = 1; b < 8; ++b) sq[b] = sq[b - 1] * sq[b - 1];

    // Window: w[t] = 1.1^e, e = t for t<256 else 510-t  (e <= 255 fits 8 bits)
    for (int t = tid; t < WIN; t += 128) {
        const int e = (t < LL) ? t : (2 * LL - 2 - t);
        double p = 1.0;
        #pragma unroll
        for (int b = 0; b < 8; ++b)
            if ((e >> b) & 1) p *= sq[b];
        w[t] = p;
    }
    __syncthreads();

    const int warp = tid >> 5;
    const int lane = tid & 31;

    // dot = sum_k noise[row=warp][frame + k] * w[k]; wsum alongside
    const float* nr = noise + warp * NOISE_LEN + frame;
    double dot = 0.0, wsum = 0.0;
    for (int k = lane; k < WIN; k += 32) {
        dot = fma((double)__ldg(nr + k), w[k], dot);
        wsum += w[k];
    }
    #pragma unroll
    for (int off = 16; off > 0; off >>= 1) {
        dot  += __shfl_down_sync(0xffffffffu, dot, off);
        wsum += __shfl_down_sync(0xffffffffu, wsum, off);
    }
    if (lane == 0) {
        wv_sh[warp] = dot;
        if (warp == 0) wsum_sh = wsum;
    }
    __syncthreads();

    if (tid < 4) vmax[tid] = fmax(wv_sh[tid] / wsum_sh, 0.0);
    __syncthreads();

    if (tid < 9) {
        const double s = vmax[0] + vmax[1] + vmax[2] + vmax[3];
        double wp = vmax[0] * (double)__ldg(basis + 0 + tid)
                  + vmax[1] * (double)__ldg(basis + 9 + tid)
                  + vmax[2] * (double)__ldg(basis + 18 + tid)
                  + vmax[3] * (double)__ldg(basis + 27 + tid);
        if (tid == 0 || tid == 4 || tid == 8) wp += 4.0 - s;
        wp_sh[tid] = wp;
    }
    __syncthreads();

    if (tid < 9) {
        const int row = tid / 3, col = tid % 3;
        const double inv223 = 1.0 / 223.0;
        // T[i][c] of  Wp @ (T(-0.5,-0.5) @ S(1/223,1/223))
        double Trow, T2;
        if (col < 2) {
            Trow = wp_sh[row * 3 + col] * inv223;
            T2   = wp_sh[2 * 3 + col] * inv223;
        } else {
            Trow = -0.5 * wp_sh[row * 3 + 0] - 0.5 * wp_sh[row * 3 + 1] + wp_sh[row * 3 + 2];
            T2   = -0.5 * wp_sh[2 * 3 + 0] - 0.5 * wp_sh[2 * 3 + 1] + wp_sh[2 * 3 + 2];
        }
        // A = S(223,223) @ T(0.5,0.5)
        const double Mel = (row < 2) ? (223.0 * Trow + 111.5 * T2) : T2;
        g_M[frame * 9 + tid] = (float)Mel;
    }
}

// ---------------------------------------------------------------------------
// Kernel 2: per-pixel projective warp + bilinear sample.
// Row pair of taps loaded as 2x LDG.128 (+ predicated LDG.32), selected with
// a two-level FSEL shifter. Warp-uniform OOB early-out.
// ---------------------------------------------------------------------------
__global__ __launch_bounds__(256) void vrp_warp_bilinear(const float* __restrict__ x,
                                                         float* __restrict__ out) {
    const int l = blockIdx.z;
    const int c = blockIdx.x * 32 + threadIdx.x;
    const int r = blockIdx.y * 8 + threadIdx.y;

    const float* Mp = g_M + l * 9;
    const float m0 = __ldg(Mp + 0), m1 = __ldg(Mp + 1), m2 = __ldg(Mp + 2);
    const float m3 = __ldg(Mp + 3), m4 = __ldg(Mp + 4), m5 = __ldg(Mp + 5);
    const float m6 = __ldg(Mp + 6), m7 = __ldg(Mp + 7), m8 = __ldg(Mp + 8);

    const float fc = (float)c, fr = (float)r;
    const float pz = fmaf(m6, fc, fmaf(m7, fr, m8));
    const float sx = fmaf(m0, fc, fmaf(m1, fr, m2)) / pz;
    const float sy = fmaf(m3, fc, fmaf(m4, fr, m5)) / pz;

    const float x0f = floorf(sx), y0f = floorf(sy);
    const float wx = sx - x0f, wy = sy - y0f;

    const bool vxL = (x0f >= 0.f)  && (x0f <= 223.f);
    const bool vxR = (x0f >= -1.f) && (x0f <= 222.f);
    const bool vyT = (y0f >= 0.f)  && (y0f <= 223.f);
    const bool vyB = (y0f >= -1.f) && (y0f <= 222.f);

    float* o = out + ((size_t)(l * HH + r) * WW + c) * CC;

    const bool any = (vxL || vxR) && (vyT || vyB);
    if (!__any_sync(0xffffffffu, any)) {
        o[0] = 0.f; o[1] = 0.f; o[2] = 0.f;
        return;
    }

    const float omwx = 1.f - wx, omwy = 1.f - wy;
    const float wTL = (vyT && vxL) ? omwy * omwx : 0.f;
    const float wTR = (vyT && vxR) ? omwy * wx   : 0.f;
    const float wBL = (vyB && vxL) ? wy * omwx   : 0.f;
    const float wBR = (vyB && vxR) ? wy * wx     : 0.f;

    const int x0 = (int)x0f;            // cvt saturates for inf; weights gate it
    const int y0 = (int)y0f;
    const int xb = min(max(x0, 0), WW - 2);
    const int yT = min(max(y0, 0), HH - 1);
    const int yB = min(max(y0 + 1, 0), HH - 1);

    // Map tap weights onto loaded slots (slot0 = col xb, slot1 = col xb+1)
    const bool eq  = (x0 == xb);        // normal case
    const bool sm1 = (x0 + 1 == xb);    // x0 == -1: R tap sits in slot0
    const bool sp1 = (x0 - 1 == xb);    // x0 == 223: L tap sits in slot1
    const float wT0 = eq ? wTL : (sm1 ? wTR : 0.f);
    const float wT1 = eq ? wTR : (sp1 ? wTL : 0.f);
    const float wB0 = eq ? wBL : (sm1 ? wBR : 0.f);
    const float wB1 = eq ? wBR : (sp1 ? wBL : 0.f);

    const float* img = x + (size_t)l * FRAME_FLOATS;
    const float4* img4 = (const float4*)img;

    const int fT = (yT * WW + xb) * 3;
    const int fB = (yB * WW + xb) * 3;
    const int s = fT & 3;               // identical for both rows (672 % 4 == 0)
    const bool b2 = (s & 2) != 0;
    const bool b1 = (s & 1) != 0;

    float acc0 = 0.f, acc1 = 0.f, acc2 = 0.f;

    #pragma unroll
    for (int rowi = 0; rowi < 2; ++rowi) {
        const int f = rowi ? fB : fT;
        const float w0s = rowi ? wB0 : wT0;
        const float w1s = rowi ? wB1 : wT1;

        const int a = f >> 2;
        const float4 v0 = __ldg(img4 + a);
        const float4 v1 = __ldg(img4 + a + 1);
        const float d8 = (s == 3) ? __ldg(img + (size_t)(a + 2) * 4) : 0.f;

        // e[j] = d[s+j], d = {v0.x..w, v1.x..w, d8}
        const float t0 = b2 ? v0.z : v0.x;
        const float t1 = b2 ? v0.w : v0.y;
        const float t2 = b2 ? v1.x : v0.z;
        const float t3 = b2 ? v1.y : v0.w;
        const float t4 = b2 ? v1.z : v1.x;
        const float t5 = b2 ? v1.w : v1.y;
        const float t6 = b2 ? d8   : v1.z;

        const float e0 = b1 ? t1 : t0;
        const float e1 = b1 ? t2 : t1;
        const float e2 = b1 ? t3 : t2;
        const float e3 = b1 ? t4 : t3;
        const float e4 = b1 ? t5 : t4;
        const float e5 = b1 ? t6 : t5;

        acc0 = fmaf(w0s, e0, acc0);
        acc1 = fmaf(w0s, e1, acc1);
        acc2 = fmaf(w0s, e2, acc2);
        acc0 = fmaf(w1s, e3, acc0);
        acc1 = fmaf(w1s, e4, acc1);
        acc2 = fmaf(w1s, e5, acc2);
    }

    o[0] = acc0;
    o[1] = acc1;
    o[2] = acc2;
}

// ---------------------------------------------------------------------------
// Launch: inputs in metadata order: x (f32), noise (f32), warp_basis (f32).
// ---------------------------------------------------------------------------
extern "C" void kernel_launch(void* const* d_in, const int* in_sizes, int n_in,
                              void* d_out, int out_size) {
    const float* x     = (const float*)d_in[0];
    const float* noise = (const float*)d_in[1];
    const float* basis = (const float*)d_in[2];
    float* out = (float*)d_out;

    vrp_matrices<<<LL, 128>>>(noise, basis);

    dim3 block(32, 8, 1);
    dim3 grid(WW / 32, HH / 8, LL);  // 7 x 28 x 256
    vrp_warp_bilinear<<<grid, block>>>(x, out);
}

// round 4
// speedup vs baseline: 6.0052x; 1.0042x over previous
#include <cuda_runtime.h>
#include <math.h>

// Problem constants (fixed shapes from reference)
#define HH 224
#define WW 224
#define CC 3
#define LL 256            // B*F = 8*32
#define NOISE_LEN 766     // 3L-2
#define WIN 511           // 2L-1
#define FRAME_FLOATS (HH * WW * CC)   // 150528

// Per-frame 3x3 matrices (row-major), produced by kernel 1, consumed by kernel 2.
__device__ float g_M[LL * 9];

// ---------------------------------------------------------------------------
// Kernel 1: fused smoothing + matrix assembly. One block per frame (256 blocks
// of 128 threads). Warp w computes the dot of noise row w with the symmetric
// exponential window (fp64, built via binary exponentiation — no pow()).
// ---------------------------------------------------------------------------
__global__ __launch_bounds__(128) void vrp_matrices(const float* __restrict__ noise,
                                                    const float* __restrict__ basis) {
    __shared__ double w[WIN];
    __shared__ double wv_sh[4];
    __shared__ double vmax[4];
    __shared__ double wp_sh[9];
    __shared__ double wsum_sh;

    const int tid = threadIdx.x;
    const int frame = blockIdx.x;

    // Binary powers of 1.1: sq[b] = 1.1^(2^b)
    double sq[8];
    sq[0] = 1.1;
    #pragma unroll
    for (int b = 1; b < 8; ++b) sq[b] = sq[b - 1] * sq[b - 1];

    // Window: w[t] = 1.1^e, e = t for t<256 else 510-t
    for (int t = tid; t < WIN; t += 128) {
        const int e = (t < LL) ? t : (2 * LL - 2 - t);
        double p = 1.0;
        #pragma unroll
        for (int b = 0; b < 8; ++b)
            if ((e >> b) & 1) p *= sq[b];
        w[t] = p;
    }
    __syncthreads();

    const int warp = tid >> 5;
    const int lane = tid & 31;

    const float* nr = noise + warp * NOISE_LEN + frame;
    double dot = 0.0, wsum = 0.0;
    for (int k = lane; k < WIN; k += 32) {
        dot = fma((double)__ldg(nr + k), w[k], dot);
        wsum += w[k];
    }
    #pragma unroll
    for (int off = 16; off > 0; off >>= 1) {
        dot  += __shfl_down_sync(0xffffffffu, dot, off);
        wsum += __shfl_down_sync(0xffffffffu, wsum, off);
    }
    if (lane == 0) {
        wv_sh[warp] = dot;
        if (warp == 0) wsum_sh = wsum;
    }
    __syncthreads();

    if (tid < 4) vmax[tid] = fmax(wv_sh[tid] / wsum_sh, 0.0);
    __syncthreads();

    if (tid < 9) {
        const double s = vmax[0] + vmax[1] + vmax[2] + vmax[3];
        double wp = vmax[0] * (double)__ldg(basis + 0 + tid)
                  + vmax[1] * (double)__ldg(basis + 9 + tid)
                  + vmax[2] * (double)__ldg(basis + 18 + tid)
                  + vmax[3] * (double)__ldg(basis + 27 + tid);
        if (tid == 0 || tid == 4 || tid == 8) wp += 4.0 - s;
        wp_sh[tid] = wp;
    }
    __syncthreads();

    if (tid < 9) {
        const int row = tid / 3, col = tid % 3;
        const double inv223 = 1.0 / 223.0;
        double Trow, T2;
        if (col < 2) {
            Trow = wp_sh[row * 3 + col] * inv223;
            T2   = wp_sh[2 * 3 + col] * inv223;
        } else {
            Trow = -0.5 * wp_sh[row * 3 + 0] - 0.5 * wp_sh[row * 3 + 1] + wp_sh[row * 3 + 2];
            T2   = -0.5 * wp_sh[2 * 3 + 0] - 0.5 * wp_sh[2 * 3 + 1] + wp_sh[2 * 3 + 2];
        }
        const double Mel = (row < 2) ? (223.0 * Trow + 111.5 * T2) : T2;
        g_M[frame * 9 + tid] = (float)Mel;
    }
}

// ---------------------------------------------------------------------------
// Kernel 2: per-pixel projective warp + bilinear sample.
// - M staged in shared (broadcast LDS, no per-thread uniform LDGs)
// - loads: 2x LDG.128 per bilinear row + predicated LDG.32, FSEL shifter
// - stores: warp repacks 96 floats through shared -> 24x STG.128 (3 lines)
// ---------------------------------------------------------------------------
__global__ __launch_bounds__(256) void vrp_warp_bilinear(const float* __restrict__ x,
                                                         float* __restrict__ out) {
    __shared__ float Ms[9];
    __shared__ __align__(16) float stage[8][96];   // per-warp output staging

    const int l = blockIdx.z;
    const int wy8 = threadIdx.y;          // warp id in block (row within tile)
    const int lane = threadIdx.x;
    const int c = blockIdx.x * 32 + lane;
    const int r = blockIdx.y * 8 + wy8;

    if (wy8 == 0 && lane < 9) Ms[lane] = g_M[l * 9 + lane];
    __syncthreads();

    const float fc = (float)c, fr = (float)r;
    const float pz = fmaf(Ms[6], fc, fmaf(Ms[7], fr, Ms[8]));
    const float inv = __fdividef(1.f, pz);
    const float sx = fmaf(Ms[0], fc, fmaf(Ms[1], fr, Ms[2])) * inv;
    const float sy = fmaf(Ms[3], fc, fmaf(Ms[4], fr, Ms[5])) * inv;

    const float x0f = floorf(sx), y0f = floorf(sy);
    const float wx = sx - x0f, wy = sy - y0f;

    const bool vxL = (x0f >= 0.f)  && (x0f <= 223.f);
    const bool vxR = (x0f >= -1.f) && (x0f <= 222.f);
    const bool vyT = (y0f >= 0.f)  && (y0f <= 223.f);
    const bool vyB = (y0f >= -1.f) && (y0f <= 222.f);

    float acc0 = 0.f, acc1 = 0.f, acc2 = 0.f;

    const bool any = (vxL || vxR) && (vyT || vyB);
    if (__any_sync(0xffffffffu, any)) {
        const float omwx = 1.f - wx, omwy = 1.f - wy;
        const float wTL = (vyT && vxL) ? omwy * omwx : 0.f;
        const float wTR = (vyT && vxR) ? omwy * wx   : 0.f;
        const float wBL = (vyB && vxL) ? wy * omwx   : 0.f;
        const float wBR = (vyB && vxR) ? wy * wx     : 0.f;

        const int x0 = (int)x0f;
        const int y0 = (int)y0f;
        const int xb = min(max(x0, 0), WW - 2);
        const int yT = min(max(y0, 0), HH - 1);
        const int yB = min(max(y0 + 1, 0), HH - 1);

        // Map tap weights onto loaded slots (slot0 = col xb, slot1 = col xb+1)
        const bool eq  = (x0 == xb);
        const bool sm1 = (x0 + 1 == xb);    // x0 == -1
        const bool sp1 = (x0 - 1 == xb);    // x0 == 223
        const float wT0 = eq ? wTL : (sm1 ? wTR : 0.f);
        const float wT1 = eq ? wTR : (sp1 ? wTL : 0.f);
        const float wB0 = eq ? wBL : (sm1 ? wBR : 0.f);
        const float wB1 = eq ? wBR : (sp1 ? wBL : 0.f);

        const float* img = x + (size_t)l * FRAME_FLOATS;
        const float4* img4 = (const float4*)img;

        const int fT = (yT * WW + xb) * 3;
        const int fB = (yB * WW + xb) * 3;
        const int s = fT & 3;               // same for both rows (672 % 4 == 0)
        const bool b2 = (s & 2) != 0;
        const bool b1 = (s & 1) != 0;

        #pragma unroll
        for (int rowi = 0; rowi < 2; ++rowi) {
            const int f = rowi ? fB : fT;
            const float w0s = rowi ? wB0 : wT0;
            const float w1s = rowi ? wB1 : wT1;

            const int a = f >> 2;
            const float4 v0 = __ldg(img4 + a);
            const float4 v1 = __ldg(img4 + a + 1);
            const float d8 = (s == 3) ? __ldg(img + (size_t)(a + 2) * 4) : 0.f;

            const float t0 = b2 ? v0.z : v0.x;
            const float t1 = b2 ? v0.w : v0.y;
            const float t2 = b2 ? v1.x : v0.z;
            const float t3 = b2 ? v1.y : v0.w;
            const float t4 = b2 ? v1.z : v1.x;
            const float t5 = b2 ? v1.w : v1.y;
            const float t6 = b2 ? d8   : v1.z;

            const float e0 = b1 ? t1 : t0;
            const float e1 = b1 ? t2 : t1;
            const float e2 = b1 ? t3 : t2;
            const float e3 = b1 ? t4 : t3;
            const float e4 = b1 ? t5 : t4;
            const float e5 = b1 ? t6 : t5;

            acc0 = fmaf(w0s, e0, acc0);
            acc1 = fmaf(w0s, e1, acc1);
            acc2 = fmaf(w0s, e2, acc2);
            acc0 = fmaf(w1s, e3, acc0);
            acc1 = fmaf(w1s, e4, acc1);
            acc2 = fmaf(w1s, e5, acc2);
        }
    }

    // Repack through shared: warp-local, then 24 lanes emit STG.128.
    stage[wy8][lane * 3 + 0] = acc0;
    stage[wy8][lane * 3 + 1] = acc1;
    stage[wy8][lane * 3 + 2] = acc2;
    __syncwarp();

    if (lane < 24) {
        const float4 v = ((const float4*)stage[wy8])[lane];
        float4* obase = (float4*)(out + ((size_t)(l * HH + r) * WW + blockIdx.x * 32) * CC);
        obase[lane] = v;
    }
}

// ---------------------------------------------------------------------------
// Launch: inputs in metadata order: x (f32), noise (f32), warp_basis (f32).
// ---------------------------------------------------------------------------
extern "C" void kernel_launch(void* const* d_in, const int* in_sizes, int n_in,
                              void* d_out, int out_size) {
    const float* x     = (const float*)d_in[0];
    const float* noise = (const float*)d_in[1];
    const float* basis = (const float*)d_in[2];
    float* out = (float*)d_out;

    vrp_matrices<<<LL, 128>>>(noise, basis);

    dim3 block(32, 8, 1);
    dim3 grid(WW / 32, HH / 8, LL);  // 7 x 28 x 256
    vrp_warp_bilinear<<<grid, block>>>(x, out);
}

// round 5
// speedup vs baseline: 6.1954x; 1.0317x over previous
#include <cuda_runtime.h>
#include <math.h>

// Problem constants (fixed shapes from reference)
#define HH 224
#define WW 224
#define CC 3
#define LL 256            // B*F = 8*32
#define NOISE_LEN 766     // 3L-2
#define WIN 511           // 2L-1
#define FRAME_FLOATS (HH * WW * CC)   // 150528
#define FRAME_F2 (FRAME_FLOATS / 2)   // 75264

// Per-frame 3x3 matrices (row-major), produced by kernel 1, consumed by kernel 2.
__device__ float g_M[LL * 9];

// ---------------------------------------------------------------------------
// Kernel 1: fused smoothing + matrix assembly. One block per frame.
// fp32 window (built by binary exponentiation) + fp32 dot; fp64 only for the
// tiny 3x3 assembly.
// ---------------------------------------------------------------------------
__global__ __launch_bounds__(128) void vrp_matrices(const float* __restrict__ noise,
                                                    const float* __restrict__ basis) {
    __shared__ float w[WIN];
    __shared__ float wv_sh[4];
    __shared__ double vmax[4];
    __shared__ double wp_sh[9];
    __shared__ float wsum_sh;

    const int tid = threadIdx.x;
    const int frame = blockIdx.x;

    // Binary powers of 1.1: sq[b] = 1.1^(2^b)
    float sq[8];
    sq[0] = 1.1f;
    #pragma unroll
    for (int b = 1; b < 8; ++b) sq[b] = sq[b - 1] * sq[b - 1];

    // Window: w[t] = 1.1^e, e = t for t<256 else 510-t
    for (int t = tid; t < WIN; t += 128) {
        const int e = (t < LL) ? t : (2 * LL - 2 - t);
        float p = 1.0f;
        #pragma unroll
        for (int b = 0; b < 8; ++b)
            if ((e >> b) & 1) p *= sq[b];
        w[t] = p;
    }
    __syncthreads();

    const int warp = tid >> 5;
    const int lane = tid & 31;

    const float* nr = noise + warp * NOISE_LEN + frame;
    float dot = 0.f, wsum = 0.f;
    for (int k = lane; k < WIN; k += 32) {
        dot = fmaf(__ldg(nr + k), w[k], dot);
        wsum += w[k];
    }
    #pragma unroll
    for (int off = 16; off > 0; off >>= 1) {
        dot  += __shfl_down_sync(0xffffffffu, dot, off);
        wsum += __shfl_down_sync(0xffffffffu, wsum, off);
    }
    if (lane == 0) {
        wv_sh[warp] = dot;
        if (warp == 0) wsum_sh = wsum;
    }
    __syncthreads();

    if (tid < 4) vmax[tid] = fmax((double)(wv_sh[tid] / wsum_sh), 0.0);
    __syncthreads();

    if (tid < 9) {
        const double s = vmax[0] + vmax[1] + vmax[2] + vmax[3];
        double wp = vmax[0] * (double)__ldg(basis + 0 + tid)
                  + vmax[1] * (double)__ldg(basis + 9 + tid)
                  + vmax[2] * (double)__ldg(basis + 18 + tid)
                  + vmax[3] * (double)__ldg(basis + 27 + tid);
        if (tid == 0 || tid == 4 || tid == 8) wp += 4.0 - s;
        wp_sh[tid] = wp;
    }
    __syncthreads();

    if (tid < 9) {
        const int row = tid / 3, col = tid % 3;
        const double inv223 = 1.0 / 223.0;
        double Trow, T2;
        if (col < 2) {
            Trow = wp_sh[row * 3 + col] * inv223;
            T2   = wp_sh[2 * 3 + col] * inv223;
        } else {
            Trow = -0.5 * wp_sh[row * 3 + 0] - 0.5 * wp_sh[row * 3 + 1] + wp_sh[row * 3 + 2];
            T2   = -0.5 * wp_sh[2 * 3 + 0] - 0.5 * wp_sh[2 * 3 + 1] + wp_sh[2 * 3 + 2];
        }
        const double Mel = (row < 2) ? (223.0 * Trow + 111.5 * T2) : T2;
        g_M[frame * 9 + tid] = (float)Mel;
    }
}

// ---------------------------------------------------------------------------
// Kernel 2: per-pixel projective warp + bilinear sample.
// - 4x LDG.64 per bilinear row, single-bit select (b1 = xb*3 & 1)
// - validity folded into slot weights h0/h1 x gyT/gyB (NaN-safe via selects)
// - warp repacks output through shared -> 24x STG.128
// ---------------------------------------------------------------------------
__global__ __launch_bounds__(256) void vrp_warp_bilinear(const float* __restrict__ x,
                                                         float* __restrict__ out) {
    __shared__ float Ms[9];
    __shared__ __align__(16) float stage[8][96];   // per-warp output staging

    const int l = blockIdx.z;
    const int wy8 = threadIdx.y;          // warp id in block (row within tile)
    const int lane = threadIdx.x;
    const int c = blockIdx.x * 32 + lane;
    const int r = blockIdx.y * 8 + wy8;

    if (wy8 == 0 && lane < 9) Ms[lane] = g_M[l * 9 + lane];
    __syncthreads();

    const float fc = (float)c, fr = (float)r;
    const float pz = fmaf(Ms[6], fc, fmaf(Ms[7], fr, Ms[8]));
    const float inv = __fdividef(1.f, pz);
    const float sx = fmaf(Ms[0], fc, fmaf(Ms[1], fr, Ms[2])) * inv;
    const float sy = fmaf(Ms[3], fc, fmaf(Ms[4], fr, Ms[5])) * inv;

    const float x0f = floorf(sx), y0f = floorf(sy);
    const float wx = sx - x0f, wy = sy - y0f;
    const float omwx = 1.f - wx, omwy = 1.f - wy;

    // y-side row weights (0 if row invalid; NaN-safe: compares false on NaN)
    const float gyT = (y0f >= 0.f  && y0f <= 223.f) ? omwy : 0.f;
    const float gyB = (y0f >= -1.f && y0f <= 222.f) ? wy   : 0.f;

    // x-side slot weights; slot0 = col xb, slot1 = col xb+1, xb = clamp(x0,0,222)
    const bool pin = (x0f >= 0.f) && (x0f <= 222.f);
    const float h0 = pin ? omwx : ((x0f == -1.f)  ? wx   : 0.f);
    const float h1 = pin ? wx   : ((x0f == 223.f) ? omwx : 0.f);

    const float wT0 = gyT * h0, wT1 = gyT * h1;
    const float wB0 = gyB * h0, wB1 = gyB * h1;

    float acc0 = 0.f, acc1 = 0.f, acc2 = 0.f;

    const bool any = (wT0 + wT1 + wB0 + wB1) > 0.f;   // weights are >= 0
    if (__any_sync(0xffffffffu, any)) {
        const int x0 = (int)x0f;                       // NaN->0, inf->sat (weights gate)
        const int xb = min(max(x0, 0), WW - 2);
        const int y0c = min(max((int)y0f, -1), HH - 1);
        const int yT = max(y0c, 0);
        const int yB = min(y0c + 1, HH - 1);

        const int x3 = 3 * xb;
        const int hx = x3 >> 1;
        const bool b1 = (x3 & 1) != 0;

        const float2* img2 = (const float2*)(x + (size_t)l * FRAME_FLOATS);

        #pragma unroll
        for (int rowi = 0; rowi < 2; ++rowi) {
            const int g = (rowi ? yB : yT) * (WW * CC / 2) + hx;   // *336
            const float w0s = rowi ? wB0 : wT0;
            const float w1s = rowi ? wB1 : wT1;

            const float2 q0 = __ldg(img2 + g);
            const float2 q1 = __ldg(img2 + g + 1);
            const float2 q2 = __ldg(img2 + g + 2);
            const float2 q3 = __ldg(img2 + min(g + 3, FRAME_F2 - 1)); // only .x used (b1)

            const float e0 = b1 ? q0.y : q0.x;
            const float e1 = b1 ? q1.x : q0.y;
            const float e2 = b1 ? q1.y : q1.x;
            const float e3 = b1 ? q2.x : q1.y;
            const float e4 = b1 ? q2.y : q2.x;
            const float e5 = b1 ? q3.x : q2.y;

            acc0 = fmaf(w0s, e0, acc0);
            acc1 = fmaf(w0s, e1, acc1);
            acc2 = fmaf(w0s, e2, acc2);
            acc0 = fmaf(w1s, e3, acc0);
            acc1 = fmaf(w1s, e4, acc1);
            acc2 = fmaf(w1s, e5, acc2);
        }
    }

    // Repack through shared: warp-local, then 24 lanes emit STG.128.
    stage[wy8][lane * 3 + 0] = acc0;
    stage[wy8][lane * 3 + 1] = acc1;
    stage[wy8][lane * 3 + 2] = acc2;
    __syncwarp();

    if (lane < 24) {
        const float4 v = ((const float4*)stage[wy8])[lane];
        float4* obase = (float4*)(out + ((size_t)(l * HH + r) * WW + blockIdx.x * 32) * CC);
        obase[lane] = v;
    }
}

// ---------------------------------------------------------------------------
// Launch: inputs in metadata order: x (f32), noise (f32), warp_basis (f32).
// ---------------------------------------------------------------------------
extern "C" void kernel_launch(void* const* d_in, const int* in_sizes, int n_in,
                              void* d_out, int out_size) {
    const float* x     = (const float*)d_in[0];
    const float* noise = (const float*)d_in[1];
    const float* basis = (const float*)d_in[2];
    float* out = (float*)d_out;

    vrp_matrices<<<LL, 128>>>(noise, basis);

    dim3 block(32, 8, 1);
    dim3 grid(WW / 32, HH / 8, LL);  // 7 x 28 x 256
    vrp_warp_bilinear<<<grid, block>>>(x, out);
}